// round 5
// baseline (speedup 1.0000x reference)
#include <cuda_runtime.h>
#include <cuda_bf16.h>
#include <math.h>

// Problem dims
#define Bn 4
#define Tn 1024
#define En 1024
#define Hn 16
#define Dn 64
#define Ln 8
#define FFn 4096
#define Vn 50257
#define BT (Bn*Tn)          // 4096
#define QKVN (3*En)         // 3072
#define ATT_SCALE (1.0f/32.0f)   // E^-0.5

// -------- scratch (static device globals; no allocation) --------
__device__ float g_x[BT*En];          // residual stream   16MB
__device__ float g_h[BT*En];          // LN output         16MB
__device__ float g_qkv[BT*QKVN];      // fused qkv         48MB
__device__ float g_att[BT*En];        // attention output  16MB
__device__ float g_ff[BT*FFn];        // FFN hidden        64MB
__device__ float g_wqkv[Ln*En*QKVN];  // packed qkv weights 100MB
__device__ float g_rownll[BT];

// ---------------- embedding ----------------
__global__ void embed_kernel(const int* __restrict__ idx,
                             const float* __restrict__ tok,
                             const float* __restrict__ pos) {
    int i = blockIdx.x * blockDim.x + threadIdx.x;   // over BT*E
    int e  = i & (En - 1);
    int bt = i >> 10;
    int t  = bt & (Tn - 1);
    g_x[i] = tok[(size_t)idx[bt] * En + e] + pos[t * En + e];
}

// ---------------- pack wq|wk|wv -> [L][E][3072] ----------------
__global__ void pack_qkv_kernel(const float* __restrict__ wq,
                                const float* __restrict__ wk,
                                const float* __restrict__ wv) {
    size_t i = (size_t)blockIdx.x * blockDim.x + threadIdx.x;  // L*E*3072
    int j   = (int)(i % QKVN);
    size_t le = i / QKVN;
    int e = (int)(le % En);
    int l = (int)(le / En);
    int sel = j >> 10;            // 0=q 1=k 2=v
    int jj  = j & 1023;
    int h = jj >> 6, d = jj & 63;
    const float* w = (sel == 0) ? wq : (sel == 1) ? wk : wv;
    g_wqkv[i] = w[((((size_t)l * Hn + h) * En) + e) * Dn + d];
}

// ---------------- layernorm (block per row, 256 thr) ----------------
__global__ void ln_kernel(const float* __restrict__ in,
                          const float* __restrict__ gamma,
                          const float* __restrict__ beta,
                          float* __restrict__ out) {
    __shared__ float rs[256], rq[256];
    int r = blockIdx.x, tid = threadIdx.x;
    float4 v = ((const float4*)(in + (size_t)r * En))[tid];
    float s = v.x + v.y + v.z + v.w;
    float q = v.x * v.x + v.y * v.y + v.z * v.z + v.w * v.w;
    rs[tid] = s; rq[tid] = q; __syncthreads();
    for (int o = 128; o > 0; o >>= 1) {
        if (tid < o) { rs[tid] += rs[tid + o]; rq[tid] += rq[tid + o]; }
        __syncthreads();
    }
    float mean = rs[0] * (1.0f / En);
    float var  = rq[0] * (1.0f / En) - mean * mean;
    float rstd = rsqrtf(var + 1e-5f);
    int e = tid * 4;
    float4 g = *(const float4*)(gamma + e);
    float4 b = *(const float4*)(beta + e);
    float4 o4;
    o4.x = (v.x - mean) * rstd * g.x + b.x;
    o4.y = (v.y - mean) * rstd * g.y + b.y;
    o4.z = (v.z - mean) * rstd * g.z + b.z;
    o4.w = (v.w - mean) * rstd * g.w + b.w;
    ((float4*)(out + (size_t)r * En))[tid] = o4;
}

// ---------------- SGEMM 128x128x16, 256 threads, 8x8 microtile ----------------
// EPI: 0 = C=acc ; 1 = C=acc+bias ; 2 = C=relu(acc+bias) ; 3 = C=Cin+acc+bias
template <int EPI>
__global__ void __launch_bounds__(256)
sgemm_kernel(const float* __restrict__ A, const float* __restrict__ B,
             const float* __restrict__ bias, const float* __restrict__ Cin,
             float* __restrict__ C, int M, int N, int K) {
    __shared__ float As[16][128];
    __shared__ float Bs[16][128];
    int tid = threadIdx.x;
    int bm = blockIdx.y * 128;
    int bn = blockIdx.x * 128;
    // float4 loads of B require 16B alignment of every row start (N % 4 == 0)
    // AND the 128-wide tile fully in bounds. LM head (N = 50257, odd) takes
    // the guarded scalar path.
    bool vecB = (bn + 128 <= N) && ((N & 3) == 0);

    int tm = (tid >> 4) * 8;
    int tn = (tid & 15) * 8;
    float acc[8][8];
#pragma unroll
    for (int i = 0; i < 8; i++)
#pragma unroll
        for (int j = 0; j < 8; j++) acc[i][j] = 0.0f;

    for (int k0 = 0; k0 < K; k0 += 16) {
#pragma unroll
        for (int i = 0; i < 2; i++) {
            int li = tid + i * 256;                 // 0..511
            int arow = li >> 2;
            int acol = (li & 3) * 4;
            float4 av = *(const float4*)(A + (size_t)(bm + arow) * K + k0 + acol);
            As[acol + 0][arow] = av.x;
            As[acol + 1][arow] = av.y;
            As[acol + 2][arow] = av.z;
            As[acol + 3][arow] = av.w;
            int brow = li >> 5;
            int bcol = (li & 31) * 4;
            if (vecB) {
                float4 bv = *(const float4*)(B + (size_t)(k0 + brow) * N + bn + bcol);
                Bs[brow][bcol + 0] = bv.x;
                Bs[brow][bcol + 1] = bv.y;
                Bs[brow][bcol + 2] = bv.z;
                Bs[brow][bcol + 3] = bv.w;
            } else {
#pragma unroll
                for (int j = 0; j < 4; j++) {
                    int n = bn + bcol + j;
                    Bs[brow][bcol + j] = (n < N) ? B[(size_t)(k0 + brow) * N + n] : 0.0f;
                }
            }
        }
        __syncthreads();
#pragma unroll
        for (int kk = 0; kk < 16; kk++) {
            float4 a0 = *(const float4*)&As[kk][tm];
            float4 a1 = *(const float4*)&As[kk][tm + 4];
            float4 b0 = *(const float4*)&Bs[kk][tn];
            float4 b1 = *(const float4*)&Bs[kk][tn + 4];
            float ar[8] = {a0.x, a0.y, a0.z, a0.w, a1.x, a1.y, a1.z, a1.w};
            float br[8] = {b0.x, b0.y, b0.z, b0.w, b1.x, b1.y, b1.z, b1.w};
#pragma unroll
            for (int i = 0; i < 8; i++)
#pragma unroll
                for (int j = 0; j < 8; j++) acc[i][j] = fmaf(ar[i], br[j], acc[i][j]);
        }
        __syncthreads();
    }

#pragma unroll
    for (int i = 0; i < 8; i++) {
        size_t crow = (size_t)(bm + tm + i);
#pragma unroll
        for (int j = 0; j < 8; j++) {
            int n = bn + tn + j;
            if (n < N) {
                size_t ci = crow * N + n;
                float v = acc[i][j];
                if (EPI >= 1) v += bias[n];
                if (EPI == 2) v = fmaxf(v, 0.0f);
                if (EPI == 3) v += Cin[ci];
                C[ci] = v;
            }
        }
    }
}

// ---------------- fused causal attention: one block per (b,h,t) ----------------
__global__ void attn_kernel(const float* __restrict__ qkv, float* __restrict__ att) {
    __shared__ float qs[64];
    __shared__ float sbuf[Tn];
    __shared__ float red[128];
    int t = blockIdx.x, h = blockIdx.y, b = blockIdx.z;
    int tid = threadIdx.x;
    int btq = b * Tn + t;

    if (tid < 64) qs[tid] = qkv[(size_t)btq * QKVN + h * 64 + tid];
    __syncthreads();

    for (int s = tid; s <= t; s += 128) {
        const float* krow = qkv + (size_t)(b * Tn + s) * QKVN + En + h * 64;
        float a = 0.0f;
#pragma unroll
        for (int d = 0; d < 64; d += 4) {
            float4 kv = *(const float4*)(krow + d);
            a += qs[d] * kv.x + qs[d + 1] * kv.y + qs[d + 2] * kv.z + qs[d + 3] * kv.w;
        }
        sbuf[s] = a * ATT_SCALE;
    }
    __syncthreads();

    float m = -1e30f;
    for (int s = tid; s <= t; s += 128) m = fmaxf(m, sbuf[s]);
    red[tid] = m; __syncthreads();
    for (int o = 64; o > 0; o >>= 1) {
        if (tid < o) red[tid] = fmaxf(red[tid], red[tid + o]);
        __syncthreads();
    }
    m = red[0]; __syncthreads();

    float sum = 0.0f;
    for (int s = tid; s <= t; s += 128) {
        float e = __expf(sbuf[s] - m);
        sbuf[s] = e;
        sum += e;
    }
    red[tid] = sum; __syncthreads();
    for (int o = 64; o > 0; o >>= 1) {
        if (tid < o) red[tid] += red[tid + o];
        __syncthreads();
    }
    float inv = 1.0f / red[0];
    __syncthreads();

    int d = tid & 63, half = tid >> 6;
    float a = 0.0f;
    for (int s = half; s <= t; s += 2)
        a += sbuf[s] * qkv[(size_t)(b * Tn + s) * QKVN + 2 * En + h * 64 + d];
    red[tid] = a; __syncthreads();
    if (half == 0)
        att[(size_t)btq * En + h * 64 + d] = (red[tid] + red[tid + 64]) * inv;
}

// ---------------- loss ----------------
__global__ void loss_rows_kernel(const float* __restrict__ logits,
                                 const int* __restrict__ tgt) {
    __shared__ float red[256];
    int r = blockIdx.x, tid = threadIdx.x;
    const float* row = logits + (size_t)r * Vn;
    float m = -1e30f;
    for (int c = tid; c < Vn; c += 256) m = fmaxf(m, row[c]);
    red[tid] = m; __syncthreads();
    for (int o = 128; o > 0; o >>= 1) {
        if (tid < o) red[tid] = fmaxf(red[tid], red[tid + o]);
        __syncthreads();
    }
    m = red[0]; __syncthreads();
    float s = 0.0f;
    for (int c = tid; c < Vn; c += 256) s += __expf(row[c] - m);
    red[tid] = s; __syncthreads();
    for (int o = 128; o > 0; o >>= 1) {
        if (tid < o) red[tid] += red[tid + o];
        __syncthreads();
    }
    if (tid == 0) {
        float lse = m + logf(red[0]);
        g_rownll[r] = lse - row[tgt[r]];
    }
}

__global__ void loss_final_kernel(float* __restrict__ out) {
    __shared__ float red[256];
    int tid = threadIdx.x;
    float s = 0.0f;
    for (int i = tid; i < BT; i += 256) s += g_rownll[i];
    red[tid] = s; __syncthreads();
    for (int o = 128; o > 0; o >>= 1) {
        if (tid < o) red[tid] += red[tid + o];
        __syncthreads();
    }
    if (tid == 0) out[0] = red[0] * (1.0f / BT);
}

// ---------------- host orchestration ----------------
extern "C" void kernel_launch(void* const* d_in, const int* in_sizes, int n_in,
                              void* d_out, int out_size) {
    const int*   idx     = (const int*)  d_in[0];
    const int*   targets = (const int*)  d_in[1];
    const float* tok_emb = (const float*)d_in[2];
    const float* pos_emb = (const float*)d_in[3];
    const float* wq      = (const float*)d_in[4];
    const float* wk      = (const float*)d_in[5];
    const float* wv      = (const float*)d_in[6];
    const float* w_proj  = (const float*)d_in[7];
    const float* b_proj  = (const float*)d_in[8];
    const float* ln1_g   = (const float*)d_in[9];
    const float* ln1_b   = (const float*)d_in[10];
    const float* ln2_g   = (const float*)d_in[11];
    const float* ln2_b   = (const float*)d_in[12];
    const float* ff_w1   = (const float*)d_in[13];
    const float* ff_b1   = (const float*)d_in[14];
    const float* ff_w2   = (const float*)d_in[15];
    const float* ff_b2   = (const float*)d_in[16];
    const float* lnf_g   = (const float*)d_in[17];
    const float* lnf_b   = (const float*)d_in[18];
    const float* lm_w    = (const float*)d_in[19];
    const float* lm_b    = (const float*)d_in[20];
    float* out = (float*)d_out;

    float *px, *ph, *pqkv, *patt, *pff, *pwqkv;
    cudaGetSymbolAddress((void**)&px,    g_x);
    cudaGetSymbolAddress((void**)&ph,    g_h);
    cudaGetSymbolAddress((void**)&pqkv,  g_qkv);
    cudaGetSymbolAddress((void**)&patt,  g_att);
    cudaGetSymbolAddress((void**)&pff,   g_ff);
    cudaGetSymbolAddress((void**)&pwqkv, g_wqkv);

    embed_kernel<<<(BT * En) / 256, 256>>>(idx, tok_emb, pos_emb);
    pack_qkv_kernel<<<(Ln * En * QKVN) / 256, 256>>>(wq, wk, wv);

    for (int l = 0; l < Ln; l++) {
        ln_kernel<<<BT, 256>>>(px, ln1_g + l * En, ln1_b + l * En, ph);
        sgemm_kernel<0><<<dim3(QKVN / 128, BT / 128), 256>>>(
            ph, pwqkv + (size_t)l * En * QKVN, nullptr, nullptr, pqkv, BT, QKVN, En);
        attn_kernel<<<dim3(Tn, Hn, Bn), 128>>>(pqkv, patt);
        sgemm_kernel<3><<<dim3(En / 128, BT / 128), 256>>>(
            patt, w_proj + (size_t)l * En * En, b_proj + l * En, px, px, BT, En, En);
        ln_kernel<<<BT, 256>>>(px, ln2_g + l * En, ln2_b + l * En, ph);
        sgemm_kernel<2><<<dim3(FFn / 128, BT / 128), 256>>>(
            ph, ff_w1 + (size_t)l * En * FFn, ff_b1 + l * FFn, nullptr, pff, BT, FFn, En);
        sgemm_kernel<3><<<dim3(En / 128, BT / 128), 256>>>(
            pff, ff_w2 + (size_t)l * FFn * En, ff_b2 + l * En, px, px, BT, En, FFn);
    }

    ln_kernel<<<BT, 256>>>(px, lnf_g, lnf_b, ph);
    sgemm_kernel<1><<<dim3((Vn + 127) / 128, BT / 128), 256>>>(
        ph, lm_w, lm_b, nullptr, out, BT, Vn, En);

    loss_rows_kernel<<<BT, 256>>>(out, targets);
    if ((size_t)out_size > (size_t)BT * Vn) {
        loss_final_kernel<<<1, 256>>>(out + (size_t)BT * Vn);
    }
}

// round 6
// speedup vs baseline: 1.1145x; 1.1145x over previous
#include <cuda_runtime.h>
#include <cuda_bf16.h>
#include <math.h>

// Problem dims
#define Bn 4
#define Tn 1024
#define En 1024
#define Hn 16
#define Dn 64
#define Ln 8
#define FFn 4096
#define Vn 50257
#define VnPad 50304                 // Vn rounded up to multiple of 128
#define BT (Bn*Tn)          // 4096
#define QKVN (3*En)         // 3072
#define ATT_SCALE (1.0f/32.0f)   // E^-0.5

// -------- scratch (static device globals; no allocation) --------
__device__ float g_x[BT*En];           // residual stream   16MB
__device__ float g_h[BT*En];           // LN output         16MB
__device__ float g_qkv[BT*QKVN];       // fused qkv         48MB
__device__ float g_att[BT*En];         // attention output  16MB
__device__ float g_ff[BT*FFn];         // FFN hidden        64MB
__device__ float g_wqkv[Ln*En*QKVN];   // packed qkv weights 100MB
__device__ float g_lmw[(size_t)En*VnPad]; // padded LM head weights 206MB
__device__ float g_rownll[BT];

// ---------------- embedding ----------------
__global__ void embed_kernel(const int* __restrict__ idx,
                             const float* __restrict__ tok,
                             const float* __restrict__ pos) {
    int i = blockIdx.x * blockDim.x + threadIdx.x;   // over BT*E
    int e  = i & (En - 1);
    int bt = i >> 10;
    int t  = bt & (Tn - 1);
    g_x[i] = tok[(size_t)idx[bt] * En + e] + pos[t * En + e];
}

// ---------------- pack wq|wk|wv -> [L][E][3072] ----------------
__global__ void pack_qkv_kernel(const float* __restrict__ wq,
                                const float* __restrict__ wk,
                                const float* __restrict__ wv) {
    size_t i = (size_t)blockIdx.x * blockDim.x + threadIdx.x;  // L*E*3072
    int j   = (int)(i % QKVN);
    size_t le = i / QKVN;
    int e = (int)(le % En);
    int l = (int)(le / En);
    int sel = j >> 10;            // 0=q 1=k 2=v
    int jj  = j & 1023;
    int h = jj >> 6, d = jj & 63;
    const float* w = (sel == 0) ? wq : (sel == 1) ? wk : wv;
    g_wqkv[i] = w[((((size_t)l * Hn + h) * En) + e) * Dn + d];
}

// ---------------- pad lm_w [E][Vn] -> g_lmw [E][VnPad] (zero pad) ----------------
__global__ void pad_lmw_kernel(const float* __restrict__ lm_w) {
    size_t i = (size_t)blockIdx.x * blockDim.x + threadIdx.x;  // over En*VnPad
    if (i >= (size_t)En * VnPad) return;
    int col = (int)(i % VnPad);
    int row = (int)(i / VnPad);
    g_lmw[i] = (col < Vn) ? lm_w[(size_t)row * Vn + col] : 0.0f;
}

// ---------------- layernorm (block per row, 256 thr) ----------------
__global__ void ln_kernel(const float* __restrict__ in,
                          const float* __restrict__ gamma,
                          const float* __restrict__ beta,
                          float* __restrict__ out) {
    __shared__ float rs[256], rq[256];
    int r = blockIdx.x, tid = threadIdx.x;
    float4 v = ((const float4*)(in + (size_t)r * En))[tid];
    float s = v.x + v.y + v.z + v.w;
    float q = v.x * v.x + v.y * v.y + v.z * v.z + v.w * v.w;
    rs[tid] = s; rq[tid] = q; __syncthreads();
    for (int o = 128; o > 0; o >>= 1) {
        if (tid < o) { rs[tid] += rs[tid + o]; rq[tid] += rq[tid + o]; }
        __syncthreads();
    }
    float mean = rs[0] * (1.0f / En);
    float var  = rq[0] * (1.0f / En) - mean * mean;
    float rstd = rsqrtf(var + 1e-5f);
    int e = tid * 4;
    float4 g = *(const float4*)(gamma + e);
    float4 b = *(const float4*)(beta + e);
    float4 o4;
    o4.x = (v.x - mean) * rstd * g.x + b.x;
    o4.y = (v.y - mean) * rstd * g.y + b.y;
    o4.z = (v.z - mean) * rstd * g.z + b.z;
    o4.w = (v.w - mean) * rstd * g.w + b.w;
    ((float4*)(out + (size_t)r * En))[tid] = o4;
}

// ---------------- SGEMM 128x128x16, 256 threads, 8x8 microtile ----------------
// EPI: 0 = C=acc ; 1 = C=acc+bias ; 2 = C=relu(acc+bias) ; 3 = C=Cin+acc+bias
// N  = valid output columns (C store guard, bias guard)
// Nb = valid B columns (>= N when padded), ldb = B row stride
template <int EPI>
__global__ void __launch_bounds__(256)
sgemm_kernel(const float* __restrict__ A, const float* __restrict__ B,
             const float* __restrict__ bias, const float* __restrict__ Cin,
             float* __restrict__ C, int M, int N, int K, int Nb, int ldb) {
    __shared__ float As[16][128];
    __shared__ float Bs[16][128];
    int tid = threadIdx.x;
    int bm = blockIdx.y * 128;
    int bn = blockIdx.x * 128;
    // float4 loads of B need 16B-aligned rows (ldb % 4 == 0) and a fully
    // in-bounds 128-wide tile within the (padded) B width Nb.
    bool vecB = (bn + 128 <= Nb) && ((ldb & 3) == 0);

    int tm = (tid >> 4) * 8;
    int tn = (tid & 15) * 8;
    float acc[8][8];
#pragma unroll
    for (int i = 0; i < 8; i++)
#pragma unroll
        for (int j = 0; j < 8; j++) acc[i][j] = 0.0f;

    for (int k0 = 0; k0 < K; k0 += 16) {
#pragma unroll
        for (int i = 0; i < 2; i++) {
            int li = tid + i * 256;                 // 0..511
            int arow = li >> 2;
            int acol = (li & 3) * 4;
            float4 av = *(const float4*)(A + (size_t)(bm + arow) * K + k0 + acol);
            As[acol + 0][arow] = av.x;
            As[acol + 1][arow] = av.y;
            As[acol + 2][arow] = av.z;
            As[acol + 3][arow] = av.w;
            int brow = li >> 5;
            int bcol = (li & 31) * 4;
            if (vecB) {
                float4 bv = *(const float4*)(B + (size_t)(k0 + brow) * ldb + bn + bcol);
                Bs[brow][bcol + 0] = bv.x;
                Bs[brow][bcol + 1] = bv.y;
                Bs[brow][bcol + 2] = bv.z;
                Bs[brow][bcol + 3] = bv.w;
            } else {
#pragma unroll
                for (int j = 0; j < 4; j++) {
                    int n = bn + bcol + j;
                    Bs[brow][bcol + j] = (n < Nb) ? B[(size_t)(k0 + brow) * ldb + n] : 0.0f;
                }
            }
        }
        __syncthreads();
#pragma unroll
        for (int kk = 0; kk < 16; kk++) {
            float4 a0 = *(const float4*)&As[kk][tm];
            float4 a1 = *(const float4*)&As[kk][tm + 4];
            float4 b0 = *(const float4*)&Bs[kk][tn];
            float4 b1 = *(const float4*)&Bs[kk][tn + 4];
            float ar[8] = {a0.x, a0.y, a0.z, a0.w, a1.x, a1.y, a1.z, a1.w};
            float br[8] = {b0.x, b0.y, b0.z, b0.w, b1.x, b1.y, b1.z, b1.w};
#pragma unroll
            for (int i = 0; i < 8; i++)
#pragma unroll
                for (int j = 0; j < 8; j++) acc[i][j] = fmaf(ar[i], br[j], acc[i][j]);
        }
        __syncthreads();
    }

#pragma unroll
    for (int i = 0; i < 8; i++) {
        size_t crow = (size_t)(bm + tm + i);
#pragma unroll
        for (int j = 0; j < 8; j++) {
            int n = bn + tn + j;
            if (n < N) {
                size_t ci = crow * N + n;
                float v = acc[i][j];
                if (EPI >= 1) v += bias[n];
                if (EPI == 2) v = fmaxf(v, 0.0f);
                if (EPI == 3) v += Cin[ci];
                C[ci] = v;
            }
        }
    }
}

// ---------------- flash-style tiled causal attention ----------------
// One block = 64 query rows for one (b,h). 256 threads: thread = q*4 + c.
// Thread (q,c) owns: Q row q (full 64 d in registers), score columns
// s in [c*16, c*16+16) per K tile, output d-slice [c*16, c*16+16).
// K tile smem (pitch 68, float4-aligned) is reused as the P (probabilities)
// buffer (pitch 65) after scores are computed.
__global__ void __launch_bounds__(256)
fattn_kernel(const float* __restrict__ qkv, float* __restrict__ att) {
    __shared__ float KP[64 * 68];   // K tile (pitch 68) -> reused as P (pitch 65)
    __shared__ float Vs[64 * 64];   // V tile (pitch 64)

    int t0 = blockIdx.x * 64;
    int h = blockIdx.y, b = blockIdx.z;
    int tid = threadIdx.x;
    int q = tid >> 2, c = tid & 3;
    int tq = t0 + q;

    // load full Q row into registers (64 floats)
    float Qr[64];
    {
        size_t qbase = ((size_t)(b * Tn + tq)) * QKVN + h * 64;
#pragma unroll
        for (int j = 0; j < 64; j += 4) {
            float4 v = *(const float4*)(qkv + qbase + j);
            Qr[j] = v.x; Qr[j + 1] = v.y; Qr[j + 2] = v.z; Qr[j + 3] = v.w;
        }
    }

    float m = -1e30f, l = 0.0f;
    float acc[16];
#pragma unroll
    for (int i = 0; i < 16; i++) acc[i] = 0.0f;

    int r  = tid >> 2;            // row loaded by this thread
    int cc = (tid & 3) << 4;      // 16-float column chunk

    for (int s0 = 0; s0 <= t0; s0 += 64) {
        __syncthreads();   // previous tile's P/V reads done before overwrite
        // load K and V tiles (each thread: 16 floats of K + 16 of V)
        {
            size_t kbase = ((size_t)(b * Tn + s0 + r)) * QKVN + En + h * 64 + cc;
#pragma unroll
            for (int j = 0; j < 16; j += 4) {
                float4 kv = *(const float4*)(qkv + kbase + j);
                *(float4*)&KP[r * 68 + cc + j] = kv;
                float4 vv = *(const float4*)(qkv + kbase + En + j);
                *(float4*)&Vs[r * 64 + cc + j] = vv;
            }
        }
        __syncthreads();

        // scores for own 16 s-columns
        float sc[16];
        bool diag = (s0 == t0);
#pragma unroll
        for (int i = 0; i < 16; i++) {
            int s = c * 16 + i;
            const float4* kr = (const float4*)&KP[s * 68];
            float a = 0.0f;
#pragma unroll
            for (int d4 = 0; d4 < 16; d4++) {
                float4 kv = kr[d4];
                a = fmaf(Qr[d4 * 4 + 0], kv.x, a);
                a = fmaf(Qr[d4 * 4 + 1], kv.y, a);
                a = fmaf(Qr[d4 * 4 + 2], kv.z, a);
                a = fmaf(Qr[d4 * 4 + 3], kv.w, a);
            }
            a *= ATT_SCALE;
            if (diag && s > q) a = -1e30f;
            sc[i] = a;
        }

        // online softmax: row max across the 4 lanes of this q
        float tmax = sc[0];
#pragma unroll
        for (int i = 1; i < 16; i++) tmax = fmaxf(tmax, sc[i]);
        tmax = fmaxf(tmax, __shfl_xor_sync(0xffffffffu, tmax, 1));
        tmax = fmaxf(tmax, __shfl_xor_sync(0xffffffffu, tmax, 2));
        float newm = fmaxf(m, tmax);
        float corr = __expf(m - newm);

        float tsum = 0.0f;
#pragma unroll
        for (int i = 0; i < 16; i++) {
            float p = __expf(sc[i] - newm);
            sc[i] = p;
            tsum += p;
        }
        tsum += __shfl_xor_sync(0xffffffffu, tsum, 1);
        tsum += __shfl_xor_sync(0xffffffffu, tsum, 2);

#pragma unroll
        for (int i = 0; i < 16; i++) acc[i] *= corr;
        l = l * corr + tsum;
        m = newm;

        __syncthreads();   // all K reads done before P overwrites KP
        // write probabilities: P[q][s], pitch 65
#pragma unroll
        for (int i = 0; i < 16; i++) KP[q * 65 + c * 16 + i] = sc[i];
        __syncthreads();

        // PV: acc[k] += sum_s P[q][s] * V[s][c*16+k]
#pragma unroll 8
        for (int s = 0; s < 64; s++) {
            float p = KP[q * 65 + s];
            const float4* vr = (const float4*)&Vs[s * 64 + c * 16];
            float4 v0 = vr[0], v1 = vr[1], v2 = vr[2], v3 = vr[3];
            acc[0]  = fmaf(p, v0.x, acc[0]);  acc[1]  = fmaf(p, v0.y, acc[1]);
            acc[2]  = fmaf(p, v0.z, acc[2]);  acc[3]  = fmaf(p, v0.w, acc[3]);
            acc[4]  = fmaf(p, v1.x, acc[4]);  acc[5]  = fmaf(p, v1.y, acc[5]);
            acc[6]  = fmaf(p, v1.z, acc[6]);  acc[7]  = fmaf(p, v1.w, acc[7]);
            acc[8]  = fmaf(p, v2.x, acc[8]);  acc[9]  = fmaf(p, v2.y, acc[9]);
            acc[10] = fmaf(p, v2.z, acc[10]); acc[11] = fmaf(p, v2.w, acc[11]);
            acc[12] = fmaf(p, v3.x, acc[12]); acc[13] = fmaf(p, v3.y, acc[13]);
            acc[14] = fmaf(p, v3.z, acc[14]); acc[15] = fmaf(p, v3.w, acc[15]);
        }
    }

    float inv = 1.0f / l;
    size_t obase = ((size_t)(b * Tn + tq)) * En + h * 64 + c * 16;
#pragma unroll
    for (int j = 0; j < 16; j += 4) {
        float4 o;
        o.x = acc[j] * inv; o.y = acc[j + 1] * inv;
        o.z = acc[j + 2] * inv; o.w = acc[j + 3] * inv;
        *(float4*)(att + obase + j) = o;
    }
}

// ---------------- loss ----------------
__global__ void loss_rows_kernel(const float* __restrict__ logits,
                                 const int* __restrict__ tgt) {
    __shared__ float red[256];
    int r = blockIdx.x, tid = threadIdx.x;
    const float* row = logits + (size_t)r * Vn;
    float m = -1e30f;
    for (int c = tid; c < Vn; c += 256) m = fmaxf(m, row[c]);
    red[tid] = m; __syncthreads();
    for (int o = 128; o > 0; o >>= 1) {
        if (tid < o) red[tid] = fmaxf(red[tid], red[tid + o]);
        __syncthreads();
    }
    m = red[0]; __syncthreads();
    float s = 0.0f;
    for (int c = tid; c < Vn; c += 256) s += __expf(row[c] - m);
    red[tid] = s; __syncthreads();
    for (int o = 128; o > 0; o >>= 1) {
        if (tid < o) red[tid] += red[tid + o];
        __syncthreads();
    }
    if (tid == 0) {
        float lse = m + logf(red[0]);
        g_rownll[r] = lse - row[tgt[r]];
    }
}

__global__ void loss_final_kernel(float* __restrict__ out) {
    __shared__ float red[256];
    int tid = threadIdx.x;
    float s = 0.0f;
    for (int i = tid; i < BT; i += 256) s += g_rownll[i];
    red[tid] = s; __syncthreads();
    for (int o = 128; o > 0; o >>= 1) {
        if (tid < o) red[tid] += red[tid + o];
        __syncthreads();
    }
    if (tid == 0) out[0] = red[0] * (1.0f / BT);
}

// ---------------- host orchestration ----------------
extern "C" void kernel_launch(void* const* d_in, const int* in_sizes, int n_in,
                              void* d_out, int out_size) {
    const int*   idx     = (const int*)  d_in[0];
    const int*   targets = (const int*)  d_in[1];
    const float* tok_emb = (const float*)d_in[2];
    const float* pos_emb = (const float*)d_in[3];
    const float* wq      = (const float*)d_in[4];
    const float* wk      = (const float*)d_in[5];
    const float* wv      = (const float*)d_in[6];
    const float* w_proj  = (const float*)d_in[7];
    const float* b_proj  = (const float*)d_in[8];
    const float* ln1_g   = (const float*)d_in[9];
    const float* ln1_b   = (const float*)d_in[10];
    const float* ln2_g   = (const float*)d_in[11];
    const float* ln2_b   = (const float*)d_in[12];
    const float* ff_w1   = (const float*)d_in[13];
    const float* ff_b1   = (const float*)d_in[14];
    const float* ff_w2   = (const float*)d_in[15];
    const float* ff_b2   = (const float*)d_in[16];
    const float* lnf_g   = (const float*)d_in[17];
    const float* lnf_b   = (const float*)d_in[18];
    const float* lm_w    = (const float*)d_in[19];
    const float* lm_b    = (const float*)d_in[20];
    float* out = (float*)d_out;

    float *px, *ph, *pqkv, *patt, *pff, *pwqkv, *plmw;
    cudaGetSymbolAddress((void**)&px,    g_x);
    cudaGetSymbolAddress((void**)&ph,    g_h);
    cudaGetSymbolAddress((void**)&pqkv,  g_qkv);
    cudaGetSymbolAddress((void**)&patt,  g_att);
    cudaGetSymbolAddress((void**)&pff,   g_ff);
    cudaGetSymbolAddress((void**)&pwqkv, g_wqkv);
    cudaGetSymbolAddress((void**)&plmw,  g_lmw);

    embed_kernel<<<(BT * En) / 256, 256>>>(idx, tok_emb, pos_emb);
    pack_qkv_kernel<<<(Ln * En * QKVN) / 256, 256>>>(wq, wk, wv);
    pad_lmw_kernel<<<(int)(((size_t)En * VnPad + 255) / 256), 256>>>(lm_w);

    for (int l = 0; l < Ln; l++) {
        ln_kernel<<<BT, 256>>>(px, ln1_g + l * En, ln1_b + l * En, ph);
        sgemm_kernel<0><<<dim3(QKVN / 128, BT / 128), 256>>>(
            ph, pwqkv + (size_t)l * En * QKVN, nullptr, nullptr, pqkv,
            BT, QKVN, En, QKVN, QKVN);
        fattn_kernel<<<dim3(Tn / 64, Hn, Bn), 256>>>(pqkv, patt);
        sgemm_kernel<3><<<dim3(En / 128, BT / 128), 256>>>(
            patt, w_proj + (size_t)l * En * En, b_proj + l * En, px, px,
            BT, En, En, En, En);
        ln_kernel<<<BT, 256>>>(px, ln2_g + l * En, ln2_b + l * En, ph);
        sgemm_kernel<2><<<dim3(FFn / 128, BT / 128), 256>>>(
            ph, ff_w1 + (size_t)l * En * FFn, ff_b1 + l * FFn, nullptr, pff,
            BT, FFn, En, FFn, FFn);
        sgemm_kernel<3><<<dim3(En / 128, BT / 128), 256>>>(
            pff, ff_w2 + (size_t)l * FFn * En, ff_b2 + l * En, px, px,
            BT, En, FFn, En, En);
    }

    ln_kernel<<<BT, 256>>>(px, lnf_g, lnf_b, ph);
    // LM head: padded, fully vectorized B loads; stores guarded to Vn
    sgemm_kernel<1><<<dim3(VnPad / 128, BT / 128), 256>>>(
        ph, plmw, lm_b, nullptr, out, BT, Vn, En, VnPad, VnPad);

    loss_rows_kernel<<<BT, 256>>>(out, targets);
    if ((size_t)out_size > (size_t)BT * Vn) {
        loss_final_kernel<<<1, 256>>>(out + (size_t)BT * Vn);
    }
}

// round 9
// speedup vs baseline: 1.1211x; 1.0059x over previous
#include <cuda_runtime.h>
#include <cuda_bf16.h>
#include <math.h>

// Problem dims
#define Bn 4
#define Tn 1024
#define En 1024
#define Hn 16
#define Dn 64
#define Ln 8
#define FFn 4096
#define Vn 50257
#define VnPad 50304                 // Vn rounded up to multiple of 128
#define BT (Bn*Tn)          // 4096
#define QKVN (3*En)         // 3072
#define ATT_SCALE (1.0f/32.0f)   // E^-0.5

// packed fp32x2 helpers (sm_103a FFMA2 path; ptxas never emits this from C++)
#define FMA_F32X2(acc, a, b) \
    asm("fma.rn.f32x2 %0, %1, %2, %3;" : "=l"(acc) : "l"(a), "l"(b), "l"(acc))
#define PACK_F32X2(out, lo, hi) \
    asm("mov.b64 %0, {%1, %2};" : "=l"(out) : "f"(lo), "f"(hi))
#define UNPACK_F32X2(lo, hi, in) \
    asm("mov.b64 {%0, %1}, %2;" : "=f"(lo), "=f"(hi) : "l"(in))

// -------- scratch (static device globals; no allocation) --------
__device__ float g_x[BT*En];           // residual stream   16MB
__device__ float g_h[BT*En];           // LN output         16MB
__device__ float g_qkv[BT*QKVN];       // fused qkv         48MB
__device__ float g_att[BT*En];         // attention output  16MB
__device__ float g_ff[BT*FFn];         // FFN hidden        64MB
__device__ float g_wqkv[Ln*En*QKVN];   // packed qkv weights 100MB
__device__ float g_lmw[(size_t)En*VnPad]; // padded LM head weights 206MB
__device__ float g_rownll[BT];

// ---------------- embedding ----------------
__global__ void embed_kernel(const int* __restrict__ idx,
                             const float* __restrict__ tok,
                             const float* __restrict__ pos) {
    int i = blockIdx.x * blockDim.x + threadIdx.x;   // over BT*E
    int e  = i & (En - 1);
    int bt = i >> 10;
    int t  = bt & (Tn - 1);
    g_x[i] = tok[(size_t)idx[bt] * En + e] + pos[t * En + e];
}

// ---------------- pack wq|wk|wv -> [L][E][3072] ----------------
__global__ void pack_qkv_kernel(const float* __restrict__ wq,
                                const float* __restrict__ wk,
                                const float* __restrict__ wv) {
    size_t i = (size_t)blockIdx.x * blockDim.x + threadIdx.x;  // L*E*3072
    int j   = (int)(i % QKVN);
    size_t le = i / QKVN;
    int e = (int)(le % En);
    int l = (int)(le / En);
    int sel = j >> 10;            // 0=q 1=k 2=v
    int jj  = j & 1023;
    int h = jj >> 6, d = jj & 63;
    const float* w = (sel == 0) ? wq : (sel == 1) ? wk : wv;
    g_wqkv[i] = w[((((size_t)l * Hn + h) * En) + e) * Dn + d];
}

// ---------------- pad lm_w [E][Vn] -> g_lmw [E][VnPad] (zero pad) ----------------
__global__ void pad_lmw_kernel(const float* __restrict__ lm_w) {
    size_t i = (size_t)blockIdx.x * blockDim.x + threadIdx.x;  // over En*VnPad
    if (i >= (size_t)En * VnPad) return;
    int col = (int)(i % VnPad);
    int row = (int)(i / VnPad);
    g_lmw[i] = (col < Vn) ? lm_w[(size_t)row * Vn + col] : 0.0f;
}

// ---------------- layernorm (block per row, 256 thr) ----------------
__global__ void ln_kernel(const float* __restrict__ in,
                          const float* __restrict__ gamma,
                          const float* __restrict__ beta,
                          float* __restrict__ out) {
    __shared__ float rs[256], rq[256];
    int r = blockIdx.x, tid = threadIdx.x;
    float4 v = ((const float4*)(in + (size_t)r * En))[tid];
    float s = v.x + v.y + v.z + v.w;
    float q = v.x * v.x + v.y * v.y + v.z * v.z + v.w * v.w;
    rs[tid] = s; rq[tid] = q; __syncthreads();
    for (int o = 128; o > 0; o >>= 1) {
        if (tid < o) { rs[tid] += rs[tid + o]; rq[tid] += rq[tid + o]; }
        __syncthreads();
    }
    float mean = rs[0] * (1.0f / En);
    float var  = rq[0] * (1.0f / En) - mean * mean;
    float rstd = rsqrtf(var + 1e-5f);
    int e = tid * 4;
    float4 g = *(const float4*)(gamma + e);
    float4 b = *(const float4*)(beta + e);
    float4 o4;
    o4.x = (v.x - mean) * rstd * g.x + b.x;
    o4.y = (v.y - mean) * rstd * g.y + b.y;
    o4.z = (v.z - mean) * rstd * g.z + b.z;
    o4.w = (v.w - mean) * rstd * g.w + b.w;
    ((float4*)(out + (size_t)r * En))[tid] = o4;
}

// ---------------- SGEMM 128x128x16, 256 threads, 8x8 microtile, FFMA2 core ----
// EPI: 0 = C=acc ; 1 = C=acc+bias ; 2 = C=relu(acc+bias) ; 3 = C=Cin+acc+bias
// N  = valid output columns (C store guard, bias guard)
// Nb = valid B columns (>= N when padded), ldb = B row stride
template <int EPI>
__global__ void __launch_bounds__(256)
sgemm_kernel(const float* __restrict__ A, const float* __restrict__ B,
             const float* __restrict__ bias, const float* __restrict__ Cin,
             float* __restrict__ C, int M, int N, int K, int Nb, int ldb) {
    __shared__ float As[16][128];
    __shared__ float Bs[16][128];
    int tid = threadIdx.x;
    int bm = blockIdx.y * 128;
    int bn = blockIdx.x * 128;
    bool vecB = (bn + 128 <= Nb) && ((ldb & 3) == 0);

    int tm = (tid >> 4) * 8;
    int tn = (tid & 15) * 8;
    // accumulators as packed f32x2: acc2[i][jp] covers columns (2jp, 2jp+1)
    unsigned long long acc2[8][4];
#pragma unroll
    for (int i = 0; i < 8; i++)
#pragma unroll
        for (int j = 0; j < 4; j++) acc2[i][j] = 0ull;

    for (int k0 = 0; k0 < K; k0 += 16) {
#pragma unroll
        for (int i = 0; i < 2; i++) {
            int li = tid + i * 256;                 // 0..511
            int arow = li >> 2;
            int acol = (li & 3) * 4;
            float4 av = *(const float4*)(A + (size_t)(bm + arow) * K + k0 + acol);
            As[acol + 0][arow] = av.x;
            As[acol + 1][arow] = av.y;
            As[acol + 2][arow] = av.z;
            As[acol + 3][arow] = av.w;
            int brow = li >> 5;
            int bcol = (li & 31) * 4;
            if (vecB) {
                float4 bv = *(const float4*)(B + (size_t)(k0 + brow) * ldb + bn + bcol);
                Bs[brow][bcol + 0] = bv.x;
                Bs[brow][bcol + 1] = bv.y;
                Bs[brow][bcol + 2] = bv.z;
                Bs[brow][bcol + 3] = bv.w;
            } else {
#pragma unroll
                for (int j = 0; j < 4; j++) {
                    int n = bn + bcol + j;
                    Bs[brow][bcol + j] = (n < Nb) ? B[(size_t)(k0 + brow) * ldb + n] : 0.0f;
                }
            }
        }
        __syncthreads();
#pragma unroll
        for (int kk = 0; kk < 16; kk++) {
            float4 a0 = *(const float4*)&As[kk][tm];
            float4 a1 = *(const float4*)&As[kk][tm + 4];
            // B columns as packed pairs straight from smem (little-endian:
            // low half = even column). tn*4B is 32B-aligned.
            const unsigned long long* bp =
                (const unsigned long long*)&Bs[kk][tn];
            unsigned long long b0 = bp[0], b1 = bp[1], b2 = bp[2], b3 = bp[3];
            float ar[8] = {a0.x, a0.y, a0.z, a0.w, a1.x, a1.y, a1.z, a1.w};
#pragma unroll
            for (int i = 0; i < 8; i++) {
                unsigned long long ap;
                PACK_F32X2(ap, ar[i], ar[i]);
                FMA_F32X2(acc2[i][0], ap, b0);
                FMA_F32X2(acc2[i][1], ap, b1);
                FMA_F32X2(acc2[i][2], ap, b2);
                FMA_F32X2(acc2[i][3], ap, b3);
            }
        }
        __syncthreads();
    }

#pragma unroll
    for (int i = 0; i < 8; i++) {
        size_t crow = (size_t)(bm + tm + i);
#pragma unroll
        for (int jp = 0; jp < 4; jp++) {
            float vlo, vhi;
            UNPACK_F32X2(vlo, vhi, acc2[i][jp]);
#pragma unroll
            for (int half = 0; half < 2; half++) {
                int n = bn + tn + jp * 2 + half;
                if (n < N) {
                    size_t ci = crow * N + n;
                    float v = half ? vhi : vlo;
                    if (EPI >= 1) v += bias[n];
                    if (EPI == 2) v = fmaxf(v, 0.0f);
                    if (EPI == 3) v += Cin[ci];
                    C[ci] = v;
                }
            }
        }
    }
}

// ---------------- flash-style tiled causal attention ----------------
// One block = 64 query rows for one (b,h). 256 threads: thread = q*4 + c.
__global__ void __launch_bounds__(256)
fattn_kernel(const float* __restrict__ qkv, float* __restrict__ att) {
    __shared__ float KP[64 * 68];   // K tile (pitch 68) -> reused as P (pitch 65)
    __shared__ float Vs[64 * 64];   // V tile (pitch 64)

    int t0 = blockIdx.x * 64;
    int h = blockIdx.y, b = blockIdx.z;
    int tid = threadIdx.x;
    int q = tid >> 2, c = tid & 3;
    int tq = t0 + q;

    float Qr[64];
    {
        size_t qbase = ((size_t)(b * Tn + tq)) * QKVN + h * 64;
#pragma unroll
        for (int j = 0; j < 64; j += 4) {
            float4 v = *(const float4*)(qkv + qbase + j);
            Qr[j] = v.x; Qr[j + 1] = v.y; Qr[j + 2] = v.z; Qr[j + 3] = v.w;
        }
    }

    float m = -1e30f, l = 0.0f;
    float acc[16];
#pragma unroll
    for (int i = 0; i < 16; i++) acc[i] = 0.0f;

    int r  = tid >> 2;
    int cc = (tid & 3) << 4;

    for (int s0 = 0; s0 <= t0; s0 += 64) {
        __syncthreads();
        {
            size_t kbase = ((size_t)(b * Tn + s0 + r)) * QKVN + En + h * 64 + cc;
#pragma unroll
            for (int j = 0; j < 16; j += 4) {
                float4 kv = *(const float4*)(qkv + kbase + j);
                *(float4*)&KP[r * 68 + cc + j] = kv;
                float4 vv = *(const float4*)(qkv + kbase + En + j);
                *(float4*)&Vs[r * 64 + cc + j] = vv;
            }
        }
        __syncthreads();

        float sc[16];
        bool diag = (s0 == t0);
#pragma unroll
        for (int i = 0; i < 16; i++) {
            int s = c * 16 + i;
            const float4* kr = (const float4*)&KP[s * 68];
            float a = 0.0f;
#pragma unroll
            for (int d4 = 0; d4 < 16; d4++) {
                float4 kv = kr[d4];
                a = fmaf(Qr[d4 * 4 + 0], kv.x, a);
                a = fmaf(Qr[d4 * 4 + 1], kv.y, a);
                a = fmaf(Qr[d4 * 4 + 2], kv.z, a);
                a = fmaf(Qr[d4 * 4 + 3], kv.w, a);
            }
            a *= ATT_SCALE;
            if (diag && s > q) a = -1e30f;
            sc[i] = a;
        }

        float tmax = sc[0];
#pragma unroll
        for (int i = 1; i < 16; i++) tmax = fmaxf(tmax, sc[i]);
        tmax = fmaxf(tmax, __shfl_xor_sync(0xffffffffu, tmax, 1));
        tmax = fmaxf(tmax, __shfl_xor_sync(0xffffffffu, tmax, 2));
        float newm = fmaxf(m, tmax);
        float corr = __expf(m - newm);

        float tsum = 0.0f;
#pragma unroll
        for (int i = 0; i < 16; i++) {
            float p = __expf(sc[i] - newm);
            sc[i] = p;
            tsum += p;
        }
        tsum += __shfl_xor_sync(0xffffffffu, tsum, 1);
        tsum += __shfl_xor_sync(0xffffffffu, tsum, 2);

#pragma unroll
        for (int i = 0; i < 16; i++) acc[i] *= corr;
        l = l * corr + tsum;
        m = newm;

        __syncthreads();
#pragma unroll
        for (int i = 0; i < 16; i++) KP[q * 65 + c * 16 + i] = sc[i];
        __syncthreads();

#pragma unroll 8
        for (int s = 0; s < 64; s++) {
            float p = KP[q * 65 + s];
            const float4* vr = (const float4*)&Vs[s * 64 + c * 16];
            float4 v0 = vr[0], v1 = vr[1], v2 = vr[2], v3 = vr[3];
            acc[0]  = fmaf(p, v0.x, acc[0]);  acc[1]  = fmaf(p, v0.y, acc[1]);
            acc[2]  = fmaf(p, v0.z, acc[2]);  acc[3]  = fmaf(p, v0.w, acc[3]);
            acc[4]  = fmaf(p, v1.x, acc[4]);  acc[5]  = fmaf(p, v1.y, acc[5]);
            acc[6]  = fmaf(p, v1.z, acc[6]);  acc[7]  = fmaf(p, v1.w, acc[7]);
            acc[8]  = fmaf(p, v2.x, acc[8]);  acc[9]  = fmaf(p, v2.y, acc[9]);
            acc[10] = fmaf(p, v2.z, acc[10]); acc[11] = fmaf(p, v2.w, acc[11]);
            acc[12] = fmaf(p, v3.x, acc[12]); acc[13] = fmaf(p, v3.y, acc[13]);
            acc[14] = fmaf(p, v3.z, acc[14]); acc[15] = fmaf(p, v3.w, acc[15]);
        }
    }

    float inv = 1.0f / l;
    size_t obase = ((size_t)(b * Tn + tq)) * En + h * 64 + c * 16;
#pragma unroll
    for (int j = 0; j < 16; j += 4) {
        float4 o;
        o.x = acc[j] * inv; o.y = acc[j + 1] * inv;
        o.z = acc[j + 2] * inv; o.w = acc[j + 3] * inv;
        *(float4*)(att + obase + j) = o;
    }
}

// ---------------- loss ----------------
__global__ void loss_rows_kernel(const float* __restrict__ logits,
                                 const int* __restrict__ tgt) {
    __shared__ float red[256];
    int r = blockIdx.x, tid = threadIdx.x;
    const float* row = logits + (size_t)r * Vn;
    float m = -1e30f;
    for (int c = tid; c < Vn; c += 256) m = fmaxf(m, row[c]);
    red[tid] = m; __syncthreads();
    for (int o = 128; o > 0; o >>= 1) {
        if (tid < o) red[tid] = fmaxf(red[tid], red[tid + o]);
        __syncthreads();
    }
    m = red[0]; __syncthreads();
    float s = 0.0f;
    for (int c = tid; c < Vn; c += 256) s += __expf(row[c] - m);
    red[tid] = s; __syncthreads();
    for (int o = 128; o > 0; o >>= 1) {
        if (tid < o) red[tid] += red[tid + o];
        __syncthreads();
    }
    if (tid == 0) {
        float lse = m + logf(red[0]);
        g_rownll[r] = lse - row[tgt[r]];
    }
}

__global__ void loss_final_kernel(float* __restrict__ out) {
    __shared__ float red[256];
    int tid = threadIdx.x;
    float s = 0.0f;
    for (int i = tid; i < BT; i += 256) s += g_rownll[i];
    red[tid] = s; __syncthreads();
    for (int o = 128; o > 0; o >>= 1) {
        if (tid < o) red[tid] += red[tid + o];
        __syncthreads();
    }
    if (tid == 0) out[0] = red[0] * (1.0f / BT);
}

// ---------------- host orchestration ----------------
extern "C" void kernel_launch(void* const* d_in, const int* in_sizes, int n_in,
                              void* d_out, int out_size) {
    const int*   idx     = (const int*)  d_in[0];
    const int*   targets = (const int*)  d_in[1];
    const float* tok_emb = (const float*)d_in[2];
    const float* pos_emb = (const float*)d_in[3];
    const float* wq      = (const float*)d_in[4];
    const float* wk      = (const float*)d_in[5];
    const float* wv      = (const float*)d_in[6];
    const float* w_proj  = (const float*)d_in[7];
    const float* b_proj  = (const float*)d_in[8];
    const float* ln1_g   = (const float*)d_in[9];
    const float* ln1_b   = (const float*)d_in[10];
    const float* ln2_g   = (const float*)d_in[11];
    const float* ln2_b   = (const float*)d_in[12];
    const float* ff_w1   = (const float*)d_in[13];
    const float* ff_b1   = (const float*)d_in[14];
    const float* ff_w2   = (const float*)d_in[15];
    const float* ff_b2   = (const float*)d_in[16];
    const float* lnf_g   = (const float*)d_in[17];
    const float* lnf_b   = (const float*)d_in[18];
    const float* lm_w    = (const float*)d_in[19];
    const float* lm_b    = (const float*)d_in[20];
    float* out = (float*)d_out;

    float *px, *ph, *pqkv, *patt, *pff, *pwqkv, *plmw;
    cudaGetSymbolAddress((void**)&px,    g_x);
    cudaGetSymbolAddress((void**)&ph,    g_h);
    cudaGetSymbolAddress((void**)&pqkv,  g_qkv);
    cudaGetSymbolAddress((void**)&patt,  g_att);
    cudaGetSymbolAddress((void**)&pff,   g_ff);
    cudaGetSymbolAddress((void**)&pwqkv, g_wqkv);
    cudaGetSymbolAddress((void**)&plmw,  g_lmw);

    embed_kernel<<<(BT * En) / 256, 256>>>(idx, tok_emb, pos_emb);
    pack_qkv_kernel<<<(Ln * En * QKVN) / 256, 256>>>(wq, wk, wv);
    pad_lmw_kernel<<<(int)(((size_t)En * VnPad + 255) / 256), 256>>>(lm_w);

    for (int l = 0; l < Ln; l++) {
        ln_kernel<<<BT, 256>>>(px, ln1_g + l * En, ln1_b + l * En, ph);
        sgemm_kernel<0><<<dim3(QKVN / 128, BT / 128), 256>>>(
            ph, pwqkv + (size_t)l * En * QKVN, nullptr, nullptr, pqkv,
            BT, QKVN, En, QKVN, QKVN);
        fattn_kernel<<<dim3(Tn / 64, Hn, Bn), 256>>>(pqkv, patt);
        sgemm_kernel<3><<<dim3(En / 128, BT / 128), 256>>>(
            patt, w_proj + (size_t)l * En * En, b_proj + l * En, px, px,
            BT, En, En, En, En);
        ln_kernel<<<BT, 256>>>(px, ln2_g + l * En, ln2_b + l * En, ph);
        sgemm_kernel<2><<<dim3(FFn / 128, BT / 128), 256>>>(
            ph, ff_w1 + (size_t)l * En * FFn, ff_b1 + l * FFn, nullptr, pff,
            BT, FFn, En, FFn, FFn);
        sgemm_kernel<3><<<dim3(En / 128, BT / 128), 256>>>(
            pff, ff_w2 + (size_t)l * FFn * En, ff_b2 + l * En, px, px,
            BT, En, FFn, En, En);
    }

    ln_kernel<<<BT, 256>>>(px, lnf_g, lnf_b, ph);
    sgemm_kernel<1><<<dim3(VnPad / 128, BT / 128), 256>>>(
        ph, plmw, lm_b, nullptr, out, BT, Vn, En, VnPad, VnPad);

    loss_rows_kernel<<<BT, 256>>>(out, targets);
    if ((size_t)out_size > (size_t)BT * Vn) {
        loss_final_kernel<<<1, 256>>>(out + (size_t)BT * Vn);
    }
}